// round 1
// baseline (speedup 1.0000x reference)
#include <cuda_runtime.h>

#define N_      4
#define H_      64
#define W_      64
#define INC_    256
#define CM_     64
#define OUTC_   256
#define HW_     (H_ * W_)       // 4096
#define HO_     (2 * H_)        // 128

// ---------------- scratch (device globals; no allocation allowed) ----------
__device__ float g_t1[N_ * CM_ * HW_];        // down-conv output   (4 MB)
__device__ float g_y [N_ * OUTC_ * HW_];      // out-conv on lowres (16 MB)
__device__ float g_kern[N_ * HW_ * 100];      // softmax kernels    (6.5 MB)
__device__ float g_wt[CM_ * 9 * 112];         // transposed enc weights

// ---------------- K0: transpose enc weights to [ic][tap][d][k pad 28] ------
__global__ void wt_kernel(const float* __restrict__ w_enc) {
    int idx = blockIdx.x * 256 + threadIdx.x;
    if (idx >= CM_ * 9 * 112) return;
    int ic  = idx / (9 * 112);
    int r   = idx % (9 * 112);
    int t   = r / 112;        // tap = kh*3+kw
    int dk  = r % 112;
    int d   = dk / 28;
    int k   = dk % 28;
    float v = 0.f;
    if (k < 25) {
        // w_enc layout: (100, 64, 3, 3); oc = k*4 + d
        v = w_enc[((k * 4 + d) * CM_ + ic) * 9 + t];
    }
    g_wt[idx] = v;
}

// ---------------- K1/K3: 1x1 conv as tiled SGEMM ---------------------------
// Y[n][m][p] = sum_k Wm[m][k] * X[n][k][p] (+ bias[m])
// grid: (M/64, 4096/64, N), block: 256
__global__ void conv1x1_kernel(const float* __restrict__ X,
                               const float* __restrict__ Wm,
                               const float* __restrict__ bias,
                               float* __restrict__ Y,
                               int M, int addBias) {
    __shared__ float As[32][64];   // [k][m]
    __shared__ float Bs[32][64];   // [k][p]

    int n  = blockIdx.z;
    int m0 = blockIdx.x * 64;
    int p0 = blockIdx.y * 64;
    int tid = threadIdx.x;
    int tr = tid >> 4;        // 0..15 (m group)
    int tc = tid & 15;        // 0..15 (p group)

    const float* Xn = X + (size_t)n * INC_ * HW_;

    float acc[4][4];
#pragma unroll
    for (int i = 0; i < 4; i++)
#pragma unroll
        for (int j = 0; j < 4; j++) acc[i][j] = 0.f;

    for (int k0 = 0; k0 < INC_; k0 += 32) {
        __syncthreads();
        // load A tile: 64 m x 32 k  (512 float4, 2 per thread)
#pragma unroll
        for (int it = 0; it < 2; it++) {
            int i = tid + it * 256;
            int m = i >> 3, c = i & 7;
            float4 a = *(const float4*)(Wm + (size_t)(m0 + m) * INC_ + k0 + c * 4);
            As[c * 4 + 0][m] = a.x;
            As[c * 4 + 1][m] = a.y;
            As[c * 4 + 2][m] = a.z;
            As[c * 4 + 3][m] = a.w;
        }
        // load B tile: 32 k x 64 p
#pragma unroll
        for (int it = 0; it < 2; it++) {
            int i = tid + it * 256;
            int r = i >> 4, c = i & 15;
            *(float4*)&Bs[r][c * 4] =
                *(const float4*)(Xn + (size_t)(k0 + r) * HW_ + p0 + c * 4);
        }
        __syncthreads();
#pragma unroll
        for (int kk = 0; kk < 32; kk++) {
            float4 a = *(const float4*)&As[kk][tr * 4];
            float4 b = *(const float4*)&Bs[kk][tc * 4];
            acc[0][0] += a.x * b.x; acc[0][1] += a.x * b.y; acc[0][2] += a.x * b.z; acc[0][3] += a.x * b.w;
            acc[1][0] += a.y * b.x; acc[1][1] += a.y * b.y; acc[1][2] += a.y * b.z; acc[1][3] += a.y * b.w;
            acc[2][0] += a.z * b.x; acc[2][1] += a.z * b.y; acc[2][2] += a.z * b.z; acc[2][3] += a.z * b.w;
            acc[3][0] += a.w * b.x; acc[3][1] += a.w * b.y; acc[3][2] += a.w * b.z; acc[3][3] += a.w * b.w;
        }
    }

    float* Yn = Y + ((size_t)n * M + m0) * HW_ + p0;
#pragma unroll
    for (int i = 0; i < 4; i++) {
        float bi = addBias ? bias[m0 + tr * 4 + i] : 0.f;
        float4 r;
        r.x = acc[i][0] + bi;
        r.y = acc[i][1] + bi;
        r.z = acc[i][2] + bi;
        r.w = acc[i][3] + bi;
        *(float4*)(Yn + (size_t)(tr * 4 + i) * HW_ + tc * 4) = r;
    }
}

// ---------------- K2: enc 3x3 conv + fused per-(d) softmax over 25 k -------
// grid: (8, 8, 4) tiles of 8x8 pixels; block: 256 = 64 px * 4 d
__global__ void enc_softmax_kernel(const float* __restrict__ bEnc) {
    __shared__ float patch[8][10][10];     // [ic][r][c]
    __shared__ float ws[8][9][112];        // [ic][tap][d*28 + k]

    int n  = blockIdx.z;
    int h0 = blockIdx.y * 8;
    int w0 = blockIdx.x * 8;
    int tid = threadIdx.x;
    int d  = tid & 3;
    int pg = tid >> 2;          // 0..63
    int pr = pg >> 3, pc = pg & 7;

    float acc[25];
#pragma unroll
    for (int k = 0; k < 25; k++) acc[k] = bEnc[k * 4 + d];

    for (int c0 = 0; c0 < CM_; c0 += 8) {
        __syncthreads();
        // stage input patch 8ic x 10 x 10 (zero padded)
        for (int idx = tid; idx < 800; idx += 256) {
            int ic = idx / 100, rem = idx % 100;
            int r = rem / 10, cc = rem % 10;
            int gh = h0 - 1 + r, gw = w0 - 1 + cc;
            float v = 0.f;
            if (gh >= 0 && gh < H_ && gw >= 0 && gw < W_)
                v = g_t1[(((size_t)n * CM_ + c0 + ic) * H_ + gh) * W_ + gw];
            patch[ic][r][cc] = v;
        }
        // stage transposed weights (contiguous copy)
        {
            const float* src = g_wt + (size_t)c0 * 9 * 112;
            float* dst = &ws[0][0][0];
            for (int idx = tid; idx < 8 * 9 * 112; idx += 256) dst[idx] = src[idx];
        }
        __syncthreads();

#pragma unroll 2
        for (int ici = 0; ici < 8; ici++) {
            float vv[3][3];
#pragma unroll
            for (int r = 0; r < 3; r++)
#pragma unroll
                for (int c = 0; c < 3; c++)
                    vv[r][c] = patch[ici][pr + r][pc + c];
#pragma unroll
            for (int t = 0; t < 9; t++) {
                float v = vv[t / 3][t % 3];
                const float* wp = &ws[ici][t][d * 28];
#pragma unroll
                for (int q = 0; q < 6; q++) {
                    float4 w4 = *(const float4*)(wp + q * 4);
                    acc[q * 4 + 0] += w4.x * v;
                    acc[q * 4 + 1] += w4.y * v;
                    acc[q * 4 + 2] += w4.z * v;
                    acc[q * 4 + 3] += w4.w * v;
                }
                acc[24] += wp[24] * v;
            }
        }
    }

    // in-register softmax over the 25 k values
    float mx = acc[0];
#pragma unroll
    for (int k = 1; k < 25; k++) mx = fmaxf(mx, acc[k]);
    float s = 0.f;
#pragma unroll
    for (int k = 0; k < 25; k++) {
        float e = __expf(acc[k] - mx);
        acc[k] = e;
        s += e;
    }
    float inv = 1.f / s;

    int h = h0 + pr, w = w0 + pc;
    float* o = g_kern + (((size_t)n * H_ + h) * W_ + w) * 100 + d * 25;
#pragma unroll
    for (int k = 0; k < 25; k++) o[k] = acc[k] * inv;
}

// ---------------- K4: reassembly + pixel shuffle + bias --------------------
// grid: (64 tiles, 8 o-blocks of 32, 4 n); block 256 = 64 px * 4 oq
__global__ void carafe_out_kernel(const float* __restrict__ bOut,
                                  float* __restrict__ out) {
    __shared__ float yp[144][36];     // [yy*12+xx][o], o padded to 36
    __shared__ float ks[64 * 100];    // [px][k*4 + d]

    int n  = blockIdx.z;
    int o0 = blockIdx.y * 32;
    int bx = blockIdx.x;
    int h0 = (bx >> 3) * 8, w0 = (bx & 7) * 8;
    int tid = threadIdx.x;

    // stage y patch (32 o x 12 x 12), zero padded
    for (int idx = tid; idx < 32 * 144; idx += 256) {
        int o = idx / 144, pos = idx % 144;
        int yy = pos / 12, xx = pos % 12;
        int gh = h0 - 2 + yy, gw = w0 - 2 + xx;
        float v = 0.f;
        if (gh >= 0 && gh < H_ && gw >= 0 && gw < W_)
            v = g_y[(((size_t)n * OUTC_ + o0 + o) * H_ + gh) * W_ + gw];
        yp[pos][o] = v;
    }
    // stage kernels, transposing [d][k] -> [k*4+d]
    for (int idx = tid; idx < 6400; idx += 256) {
        int px = idx / 100, r = idx % 100;
        int dd = r / 25, k = r % 25;
        int h = h0 + (px >> 3), w = w0 + (px & 7);
        ks[px * 100 + k * 4 + dd] =
            g_kern[(((size_t)n * H_ + h) * W_ + w) * 100 + r];
    }
    __syncthreads();

    int px = tid >> 2, oq = tid & 3;
    int pr = px >> 3, pc = px & 7;

    float acc[8][4];
#pragma unroll
    for (int i = 0; i < 8; i++)
#pragma unroll
        for (int d = 0; d < 4; d++) acc[i][d] = 0.f;

    for (int kh = 0; kh < 5; kh++) {
#pragma unroll
        for (int kw = 0; kw < 5; kw++) {
            float4 kv = *(const float4*)&ks[px * 100 + (kh * 5 + kw) * 4];
            const float* yr = &yp[(pr + kh) * 12 + pc + kw][oq];
#pragma unroll
            for (int i = 0; i < 8; i++) {
                float yv = yr[i * 4];
                acc[i][0] += yv * kv.x;
                acc[i][1] += yv * kv.y;
                acc[i][2] += yv * kv.z;
                acc[i][3] += yv * kv.w;
            }
        }
    }

    int oy = 2 * (h0 + pr);
    int ox = 2 * (w0 + pc);
#pragma unroll
    for (int i = 0; i < 8; i++) {
        int o = o0 + oq + 4 * i;
        float b = bOut[o];
        float* p = out + (((size_t)n * OUTC_ + o) * HO_ + oy) * HO_ + ox;
        float2 r0; r0.x = acc[i][0] + b; r0.y = acc[i][1] + b;
        float2 r1; r1.x = acc[i][2] + b; r1.y = acc[i][3] + b;
        *(float2*)p = r0;
        *(float2*)(p + HO_) = r1;
    }
}

// ---------------- launch ----------------------------------------------------
extern "C" void kernel_launch(void* const* d_in, const int* in_sizes, int n_in,
                              void* d_out, int out_size) {
    (void)in_sizes; (void)n_in; (void)out_size;
    const float* x      = (const float*)d_in[0];
    const float* w_down = (const float*)d_in[1];
    const float* b_down = (const float*)d_in[2];
    const float* w_enc  = (const float*)d_in[3];
    const float* b_enc  = (const float*)d_in[4];
    const float* w_out  = (const float*)d_in[5];
    const float* b_out  = (const float*)d_in[6];
    float* out = (float*)d_out;

    float *t1p, *yp_, *kernp;
    cudaGetSymbolAddress((void**)&t1p,   g_t1);
    cudaGetSymbolAddress((void**)&yp_,   g_y);
    cudaGetSymbolAddress((void**)&kernp, g_kern);
    (void)kernp;

    // K0: enc weight transpose
    wt_kernel<<<(CM_ * 9 * 112 + 255) / 256, 256>>>(w_enc);
    // K1: down 1x1 conv -> g_t1
    conv1x1_kernel<<<dim3(1, 64, 4), 256>>>(x, w_down, b_down, t1p, CM_, 1);
    // K3: out 1x1 conv on low-res -> g_y (bias deferred)
    conv1x1_kernel<<<dim3(4, 64, 4), 256>>>(x, w_out, nullptr, yp_, OUTC_, 0);
    // K2: enc 3x3 conv + softmax -> g_kern
    enc_softmax_kernel<<<dim3(8, 8, 4), 256>>>(b_enc);
    // K4: reassembly + pixel shuffle + bias -> out
    carafe_out_kernel<<<dim3(64, 8, 4), 256>>>(b_out, out);
}

// round 2
// speedup vs baseline: 1.4016x; 1.4016x over previous
#include <cuda_runtime.h>

#define N_      4
#define H_      64
#define W_      64
#define INC_    256
#define CM_     64
#define OUTC_   256
#define HW_     (H_ * W_)       // 4096
#define HO_     (2 * H_)        // 128
#define NCHUNK_ 8               // ic chunks for enc conv (8 ic each)

// ---------------- scratch (device globals; no allocation allowed) ----------
__device__ float g_t1[N_ * CM_ * HW_];              // down-conv output   (4 MB)
__device__ float g_y [N_ * OUTC_ * HW_];            // out-conv on lowres (16 MB)
__device__ float g_kern[N_ * 100 * HW_];            // softmax kernels, channel-major [n][r][hw]
__device__ float g_part[NCHUNK_ * N_ * 100 * HW_];  // enc conv partials  (52 MB)
__device__ float g_wt[CM_ * 9 * 112];               // transposed enc weights

__device__ __forceinline__ unsigned long long fma2(unsigned long long a,
                                                   unsigned long long b,
                                                   unsigned long long c) {
    unsigned long long d;
    asm("fma.rn.f32x2 %0, %1, %2, %3;" : "=l"(d) : "l"(a), "l"(b), "l"(c));
    return d;
}
__device__ __forceinline__ unsigned long long pack2(float x) {
    unsigned long long r;
    asm("mov.b64 %0, {%1, %1};" : "=l"(r) : "f"(x));
    return r;
}

// ---------------- K0: transpose enc weights to [ic][tap][d][k pad 28] ------
__global__ void wt_kernel(const float* __restrict__ w_enc) {
    int idx = blockIdx.x * 256 + threadIdx.x;
    if (idx >= CM_ * 9 * 112) return;
    int ic  = idx / (9 * 112);
    int r   = idx % (9 * 112);
    int t   = r / 112;        // tap = kh*3+kw
    int dk  = r % 112;
    int d   = dk / 28;
    int k   = dk % 28;
    float v = 0.f;
    if (k < 25) v = w_enc[((k * 4 + d) * CM_ + ic) * 9 + t];
    g_wt[idx] = v;
}

// ---------------- K1/K3: 1x1 conv as tiled SGEMM ---------------------------
__global__ void conv1x1_kernel(const float* __restrict__ X,
                               const float* __restrict__ Wm,
                               const float* __restrict__ bias,
                               float* __restrict__ Y,
                               int M, int addBias) {
    __shared__ float As[32][64];   // [k][m]
    __shared__ float Bs[32][64];   // [k][p]

    int n  = blockIdx.z;
    int m0 = blockIdx.x * 64;
    int p0 = blockIdx.y * 64;
    int tid = threadIdx.x;
    int tr = tid >> 4;
    int tc = tid & 15;

    const float* Xn = X + (size_t)n * INC_ * HW_;

    float acc[4][4];
#pragma unroll
    for (int i = 0; i < 4; i++)
#pragma unroll
        for (int j = 0; j < 4; j++) acc[i][j] = 0.f;

    for (int k0 = 0; k0 < INC_; k0 += 32) {
        __syncthreads();
#pragma unroll
        for (int it = 0; it < 2; it++) {
            int i = tid + it * 256;
            int m = i >> 3, c = i & 7;
            float4 a = *(const float4*)(Wm + (size_t)(m0 + m) * INC_ + k0 + c * 4);
            As[c * 4 + 0][m] = a.x;
            As[c * 4 + 1][m] = a.y;
            As[c * 4 + 2][m] = a.z;
            As[c * 4 + 3][m] = a.w;
        }
#pragma unroll
        for (int it = 0; it < 2; it++) {
            int i = tid + it * 256;
            int r = i >> 4, c = i & 15;
            *(float4*)&Bs[r][c * 4] =
                *(const float4*)(Xn + (size_t)(k0 + r) * HW_ + p0 + c * 4);
        }
        __syncthreads();
#pragma unroll
        for (int kk = 0; kk < 32; kk++) {
            float4 a = *(const float4*)&As[kk][tr * 4];
            float4 b = *(const float4*)&Bs[kk][tc * 4];
            acc[0][0] += a.x * b.x; acc[0][1] += a.x * b.y; acc[0][2] += a.x * b.z; acc[0][3] += a.x * b.w;
            acc[1][0] += a.y * b.x; acc[1][1] += a.y * b.y; acc[1][2] += a.y * b.z; acc[1][3] += a.y * b.w;
            acc[2][0] += a.z * b.x; acc[2][1] += a.z * b.y; acc[2][2] += a.z * b.z; acc[2][3] += a.z * b.w;
            acc[3][0] += a.w * b.x; acc[3][1] += a.w * b.y; acc[3][2] += a.w * b.z; acc[3][3] += a.w * b.w;
        }
    }

    float* Yn = Y + ((size_t)n * M + m0) * HW_ + p0;
#pragma unroll
    for (int i = 0; i < 4; i++) {
        float bi = addBias ? bias[m0 + tr * 4 + i] : 0.f;
        float4 r;
        r.x = acc[i][0] + bi;
        r.y = acc[i][1] + bi;
        r.z = acc[i][2] + bi;
        r.w = acc[i][3] + bi;
        *(float4*)(Yn + (size_t)(tr * 4 + i) * HW_ + tc * 4) = r;
    }
}

// ---------------- K2a: enc 3x3 conv partials (8 ic per block) --------------
// grid: (32 tiles of 8x16 px, 8 ic-chunks, 4 n); block 256 = 8 warps.
// warp wi: d = wi>>1 (warp-uniform!), 32 px per warp, 2 px per thread.
__global__ void __launch_bounds__(256, 3) enc_part_kernel() {
    __shared__ float patch[8][10][40];                 // rows padded to 40 (conflict-free)
    __shared__ __align__(16) float ws[8][9][112];      // [ic][tap][d*28+k]

    int n     = blockIdx.z;
    int chunk = blockIdx.y;
    int bx    = blockIdx.x;                 // 0..31
    int h0 = (bx >> 2) * 8;
    int w0 = (bx & 3) * 16;
    int tid  = threadIdx.x;
    int wi   = tid >> 5, lane = tid & 31;
    int d    = wi >> 1;
    int pxg  = (wi & 1) * 32 + lane;        // 0..63
    int pr   = pxg >> 3, pc = pxg & 7;      // pixels (pr, pc) and (pr, pc+8)
    int icbase = chunk * 8;

    // stage patch 8ic x 10 x 18 (zero padded at image border)
    for (int idx = tid; idx < 1440; idx += 256) {
        int ic = idx / 180, rem = idx % 180;
        int r = rem / 18, c = rem % 18;
        int gh = h0 - 1 + r, gw = w0 - 1 + c;
        float v = 0.f;
        if (gh >= 0 && gh < H_ && gw >= 0 && gw < W_)
            v = g_t1[(((size_t)n * CM_ + icbase + ic) * H_ + gh) * W_ + gw];
        patch[ic][r][c] = v;
    }
    // stage transposed weights
    {
        const float* src = g_wt + (size_t)icbase * 9 * 112;
        float* dst = &ws[0][0][0];
        for (int idx = tid; idx < 8 * 9 * 112; idx += 256) dst[idx] = src[idx];
    }
    __syncthreads();

    unsigned long long acc[2][12];
    float acc24[2];
#pragma unroll
    for (int p = 0; p < 2; p++) {
        acc24[p] = 0.f;
#pragma unroll
        for (int m = 0; m < 12; m++) acc[p][m] = 0ull;
    }

#pragma unroll 2
    for (int ici = 0; ici < 8; ici++) {
#pragma unroll
        for (int t = 0; t < 9; t++) {
            int r = t / 3, c = t % 3;
            float va = patch[ici][pr + r][pc + c];
            float vb = patch[ici][pr + r][pc + 8 + c];
            unsigned long long va2 = pack2(va);
            unsigned long long vb2 = pack2(vb);
            const ulonglong2* wp = (const ulonglong2*)&ws[ici][t][d * 28];
#pragma unroll
            for (int q = 0; q < 6; q++) {
                ulonglong2 w2 = wp[q];
                acc[0][2 * q + 0] = fma2(w2.x, va2, acc[0][2 * q + 0]);
                acc[0][2 * q + 1] = fma2(w2.y, va2, acc[0][2 * q + 1]);
                acc[1][2 * q + 0] = fma2(w2.x, vb2, acc[1][2 * q + 0]);
                acc[1][2 * q + 1] = fma2(w2.y, vb2, acc[1][2 * q + 1]);
            }
            float w24 = ws[ici][t][d * 28 + 24];
            acc24[0] += w24 * va;
            acc24[1] += w24 * vb;
        }
    }

    // store partials: layout [chunk][n][d*25+k][hw], fully coalesced
#pragma unroll
    for (int p = 0; p < 2; p++) {
        int hw = (h0 + pr) * W_ + w0 + pc + p * 8;
        float* o = g_part + ((size_t)(chunk * N_ + n) * 100 + d * 25) * HW_ + hw;
#pragma unroll
        for (int m = 0; m < 12; m++) {
            unsigned long long a = acc[p][m];
            float lo = __uint_as_float((unsigned int)a);
            float hi = __uint_as_float((unsigned int)(a >> 32));
            o[(size_t)(2 * m) * HW_]     = lo;
            o[(size_t)(2 * m + 1) * HW_] = hi;
        }
        o[(size_t)24 * HW_] = acc24[p];
    }
}

// ---------------- K2b: sum partials + bias + softmax over 25 k -------------
// grid 256 blocks x 256 threads: thread = (px, d)
__global__ void softmax_kernel(const float* __restrict__ bEnc) {
    int tid = threadIdx.x;
    int d = tid >> 6;
    int p = blockIdx.x * 64 + (tid & 63);   // 0..16383
    int n = p >> 12, hw = p & 4095;

    float v[25];
#pragma unroll
    for (int k = 0; k < 25; k++) {
        float s = bEnc[k * 4 + d];
        size_t base = ((size_t)n * 100 + d * 25 + k) * HW_ + hw;
#pragma unroll
        for (int c = 0; c < NCHUNK_; c++)
            s += g_part[(size_t)c * N_ * 100 * HW_ + base];
        v[k] = s;
    }

    float mx = v[0];
#pragma unroll
    for (int k = 1; k < 25; k++) mx = fmaxf(mx, v[k]);
    float s = 0.f;
#pragma unroll
    for (int k = 0; k < 25; k++) {
        float e = __expf(v[k] - mx);
        v[k] = e;
        s += e;
    }
    float inv = 1.f / s;

    float* o = g_kern + ((size_t)n * 100 + d * 25) * HW_ + hw;
#pragma unroll
    for (int k = 0; k < 25; k++) o[(size_t)k * HW_] = v[k] * inv;
}

// ---------------- K4: reassembly + pixel shuffle + bias --------------------
// grid: (64 tiles, 8 o-blocks of 32, 4 n); block 256 = 64 px * 4 oq
__global__ void carafe_out_kernel(const float* __restrict__ bOut,
                                  float* __restrict__ out) {
    __shared__ float yp[144][36];     // [yy*12+xx][o], o padded to 36
    __shared__ float ks[64 * 100];    // [px][k*4 + d]

    int n  = blockIdx.z;
    int o0 = blockIdx.y * 32;
    int bx = blockIdx.x;
    int h0 = (bx >> 3) * 8, w0 = (bx & 7) * 8;
    int tid = threadIdx.x;

    // stage y patch (32 o x 12 x 12), zero padded
    for (int idx = tid; idx < 32 * 144; idx += 256) {
        int o = idx / 144, pos = idx % 144;
        int yy = pos / 12, xx = pos % 12;
        int gh = h0 - 2 + yy, gw = w0 - 2 + xx;
        float v = 0.f;
        if (gh >= 0 && gh < H_ && gw >= 0 && gw < W_)
            v = g_y[(((size_t)n * OUTC_ + o0 + o) * H_ + gh) * W_ + gw];
        yp[pos][o] = v;
    }
    // stage kernels from channel-major g_kern, transposing [r][px] -> [px][k*4+d]
    for (int idx = tid; idx < 6400; idx += 256) {
        int r = idx >> 6;            // 0..99 (= dd*25 + k)
        int px = idx & 63;
        int dd = r / 25, k = r % 25;
        int h = h0 + (px >> 3), w = w0 + (px & 7);
        ks[px * 100 + k * 4 + dd] =
            g_kern[((size_t)n * 100 + r) * HW_ + h * W_ + w];
    }
    __syncthreads();

    int px = tid >> 2, oq = tid & 3;
    int pr = px >> 3, pc = px & 7;

    float acc[8][4];
#pragma unroll
    for (int i = 0; i < 8; i++)
#pragma unroll
        for (int d = 0; d < 4; d++) acc[i][d] = 0.f;

    for (int kh = 0; kh < 5; kh++) {
#pragma unroll
        for (int kw = 0; kw < 5; kw++) {
            float4 kv = *(const float4*)&ks[px * 100 + (kh * 5 + kw) * 4];
            const float* yr = &yp[(pr + kh) * 12 + pc + kw][oq];
#pragma unroll
            for (int i = 0; i < 8; i++) {
                float yv = yr[i * 4];
                acc[i][0] += yv * kv.x;
                acc[i][1] += yv * kv.y;
                acc[i][2] += yv * kv.z;
                acc[i][3] += yv * kv.w;
            }
        }
    }

    int oy = 2 * (h0 + pr);
    int ox = 2 * (w0 + pc);
#pragma unroll
    for (int i = 0; i < 8; i++) {
        int o = o0 + oq + 4 * i;
        float b = bOut[o];
        float* p = out + (((size_t)n * OUTC_ + o) * HO_ + oy) * HO_ + ox;
        float2 r0; r0.x = acc[i][0] + b; r0.y = acc[i][1] + b;
        float2 r1; r1.x = acc[i][2] + b; r1.y = acc[i][3] + b;
        *(float2*)p = r0;
        *(float2*)(p + HO_) = r1;
    }
}

// ---------------- launch ----------------------------------------------------
extern "C" void kernel_launch(void* const* d_in, const int* in_sizes, int n_in,
                              void* d_out, int out_size) {
    (void)in_sizes; (void)n_in; (void)out_size;
    const float* x      = (const float*)d_in[0];
    const float* w_down = (const float*)d_in[1];
    const float* b_down = (const float*)d_in[2];
    const float* w_enc  = (const float*)d_in[3];
    const float* b_enc  = (const float*)d_in[4];
    const float* w_out  = (const float*)d_in[5];
    const float* b_out  = (const float*)d_in[6];
    float* out = (float*)d_out;

    float *t1p, *yp_;
    cudaGetSymbolAddress((void**)&t1p, g_t1);
    cudaGetSymbolAddress((void**)&yp_, g_y);

    // K0: enc weight transpose
    wt_kernel<<<(CM_ * 9 * 112 + 255) / 256, 256>>>(w_enc);
    // K1: down 1x1 conv -> g_t1
    conv1x1_kernel<<<dim3(1, 64, 4), 256>>>(x, w_down, b_down, t1p, CM_, 1);
    // K2a: enc 3x3 conv partials -> g_part
    enc_part_kernel<<<dim3(32, NCHUNK_, 4), 256>>>();
    // K2b: sum + softmax -> g_kern (channel-major)
    softmax_kernel<<<256, 256>>>(b_enc);
    // K3: out 1x1 conv on low-res -> g_y (bias deferred)
    conv1x1_kernel<<<dim3(4, 64, 4), 256>>>(x, w_out, nullptr, yp_, OUTC_, 0);
    // K4: reassembly + pixel shuffle + bias -> out
    carafe_out_kernel<<<dim3(64, 8, 4), 256>>>(b_out, out);
}

// round 3
// speedup vs baseline: 1.4169x; 1.0109x over previous
#include <cuda_runtime.h>

#define N_      4
#define H_      64
#define W_      64
#define INC_    256
#define CM_     64
#define OUTC_   256
#define HW_     (H_ * W_)       // 4096
#define HO_     (2 * H_)        // 128
#define NCHUNK_ 4               // ic chunks for enc conv (16 ic each)

// ---------------- scratch (device globals; no allocation allowed) ----------
__device__ float g_t1[N_ * CM_ * HW_];              // down-conv output   (4 MB)
__device__ float g_y [N_ * OUTC_ * HW_];            // out-conv on lowres (16 MB)
__device__ float g_kern[N_ * 100 * HW_];            // softmax kernels, channel-major
__device__ float g_part[NCHUNK_ * N_ * 100 * HW_];  // enc conv partials  (26 MB)
__device__ float g_wt[CM_ * 9 * 112];               // transposed enc weights

__device__ __forceinline__ unsigned long long fma2(unsigned long long a,
                                                   unsigned long long b,
                                                   unsigned long long c) {
    unsigned long long d;
    asm("fma.rn.f32x2 %0, %1, %2, %3;" : "=l"(d) : "l"(a), "l"(b), "l"(c));
    return d;
}
__device__ __forceinline__ unsigned long long pack2(float x) {
    unsigned long long r;
    asm("mov.b64 %0, {%1, %1};" : "=l"(r) : "f"(x));
    return r;
}
__device__ __forceinline__ float2 unpack2(unsigned long long a) {
    float2 r;
    asm("mov.b64 {%0, %1}, %2;" : "=f"(r.x), "=f"(r.y) : "l"(a));
    return r;
}

// ---------------- K0: transpose enc weights to [ic][tap][d][k pad 28] ------
__global__ void wt_kernel(const float* __restrict__ w_enc) {
    int idx = blockIdx.x * 256 + threadIdx.x;
    if (idx >= CM_ * 9 * 112) return;
    int ic  = idx / (9 * 112);
    int r   = idx % (9 * 112);
    int t   = r / 112;
    int dk  = r % 112;
    int d   = dk / 28;
    int k   = dk % 28;
    float v = 0.f;
    if (k < 25) v = w_enc[((k * 4 + d) * CM_ + ic) * 9 + t];
    g_wt[idx] = v;
}

// ---------------- K1/K3: 1x1 conv as tiled SGEMM (f32x2) -------------------
// Y[n][m][p] = sum_k Wm[m][k] * X[n][k][p] (+ bias[m])
__global__ void conv1x1_kernel(const float* __restrict__ X,
                               const float* __restrict__ Wm,
                               const float* __restrict__ bias,
                               float* __restrict__ Y,
                               int M, int addBias) {
    __shared__ float As[32][64];                  // [k][m]
    __shared__ __align__(16) float Bs[32][64];    // [k][p]

    int n  = blockIdx.z;
    int m0 = blockIdx.x * 64;
    int p0 = blockIdx.y * 64;
    int tid = threadIdx.x;
    int tr = tid >> 4;
    int tc = tid & 15;

    const float* Xn = X + (size_t)n * INC_ * HW_;

    unsigned long long acc[4][2];
#pragma unroll
    for (int i = 0; i < 4; i++) { acc[i][0] = 0ull; acc[i][1] = 0ull; }

    for (int k0 = 0; k0 < INC_; k0 += 32) {
        __syncthreads();
#pragma unroll
        for (int it = 0; it < 2; it++) {
            int i = tid + it * 256;
            int m = i >> 3, c = i & 7;
            float4 a = *(const float4*)(Wm + (size_t)(m0 + m) * INC_ + k0 + c * 4);
            As[c * 4 + 0][m] = a.x;
            As[c * 4 + 1][m] = a.y;
            As[c * 4 + 2][m] = a.z;
            As[c * 4 + 3][m] = a.w;
        }
#pragma unroll
        for (int it = 0; it < 2; it++) {
            int i = tid + it * 256;
            int r = i >> 4, c = i & 15;
            *(float4*)&Bs[r][c * 4] =
                *(const float4*)(Xn + (size_t)(k0 + r) * HW_ + p0 + c * 4);
        }
        __syncthreads();
#pragma unroll
        for (int kk = 0; kk < 32; kk++) {
            float4 a = *(const float4*)&As[kk][tr * 4];
            ulonglong2 b2 = *(const ulonglong2*)&Bs[kk][tc * 4];
            unsigned long long a0 = pack2(a.x), a1 = pack2(a.y);
            unsigned long long a2 = pack2(a.z), a3 = pack2(a.w);
            acc[0][0] = fma2(a0, b2.x, acc[0][0]); acc[0][1] = fma2(a0, b2.y, acc[0][1]);
            acc[1][0] = fma2(a1, b2.x, acc[1][0]); acc[1][1] = fma2(a1, b2.y, acc[1][1]);
            acc[2][0] = fma2(a2, b2.x, acc[2][0]); acc[2][1] = fma2(a2, b2.y, acc[2][1]);
            acc[3][0] = fma2(a3, b2.x, acc[3][0]); acc[3][1] = fma2(a3, b2.y, acc[3][1]);
        }
    }

    float* Yn = Y + ((size_t)n * M + m0) * HW_ + p0;
#pragma unroll
    for (int i = 0; i < 4; i++) {
        float bi = addBias ? bias[m0 + tr * 4 + i] : 0.f;
        float2 lo = unpack2(acc[i][0]);
        float2 hi = unpack2(acc[i][1]);
        float4 r;
        r.x = lo.x + bi; r.y = lo.y + bi;
        r.z = hi.x + bi; r.w = hi.y + bi;
        *(float4*)(Yn + (size_t)(tr * 4 + i) * HW_ + tc * 4) = r;
    }
}

// ---------------- K2a: enc 3x3 conv partials (16 ic per block, 2 passes) ---
// grid: (32 tiles of 8x16 px, 4 ic-chunks, 4 n); block 256 = 8 warps.
__global__ void __launch_bounds__(256, 3) enc_part_kernel() {
    __shared__ float patch[8][10][40];
    __shared__ __align__(16) float ws[8][9][112];

    int n     = blockIdx.z;
    int chunk = blockIdx.y;                 // 0..3
    int bx    = blockIdx.x;                 // 0..31
    int h0 = (bx >> 2) * 8;
    int w0 = (bx & 3) * 16;
    int tid  = threadIdx.x;
    int wi   = tid >> 5, lane = tid & 31;
    int d    = wi >> 1;
    int pxg  = (wi & 1) * 32 + lane;
    int pr   = pxg >> 3, pc = pxg & 7;

    unsigned long long acc[2][12];
    float acc24[2];
#pragma unroll
    for (int p = 0; p < 2; p++) {
        acc24[p] = 0.f;
#pragma unroll
        for (int m = 0; m < 12; m++) acc[p][m] = 0ull;
    }

    for (int sc = 0; sc < 2; sc++) {
        int icbase = chunk * 16 + sc * 8;
        __syncthreads();
        for (int idx = tid; idx < 1440; idx += 256) {
            int ic = idx / 180, rem = idx % 180;
            int r = rem / 18, c = rem % 18;
            int gh = h0 - 1 + r, gw = w0 - 1 + c;
            float v = 0.f;
            if (gh >= 0 && gh < H_ && gw >= 0 && gw < W_)
                v = g_t1[(((size_t)n * CM_ + icbase + ic) * H_ + gh) * W_ + gw];
            patch[ic][r][c] = v;
        }
        {
            const float* src = g_wt + (size_t)icbase * 9 * 112;
            float* dst = &ws[0][0][0];
            for (int idx = tid; idx < 8 * 9 * 112; idx += 256) dst[idx] = src[idx];
        }
        __syncthreads();

#pragma unroll 2
        for (int ici = 0; ici < 8; ici++) {
#pragma unroll
            for (int t = 0; t < 9; t++) {
                int r = t / 3, c = t % 3;
                float va = patch[ici][pr + r][pc + c];
                float vb = patch[ici][pr + r][pc + 8 + c];
                unsigned long long va2 = pack2(va);
                unsigned long long vb2 = pack2(vb);
                const ulonglong2* wp = (const ulonglong2*)&ws[ici][t][d * 28];
#pragma unroll
                for (int q = 0; q < 6; q++) {
                    ulonglong2 w2 = wp[q];
                    acc[0][2 * q + 0] = fma2(w2.x, va2, acc[0][2 * q + 0]);
                    acc[0][2 * q + 1] = fma2(w2.y, va2, acc[0][2 * q + 1]);
                    acc[1][2 * q + 0] = fma2(w2.x, vb2, acc[1][2 * q + 0]);
                    acc[1][2 * q + 1] = fma2(w2.y, vb2, acc[1][2 * q + 1]);
                }
                float w24 = ws[ici][t][d * 28 + 24];
                acc24[0] += w24 * va;
                acc24[1] += w24 * vb;
            }
        }
    }

    // store partials: layout [chunk][n][d*25+k][hw], coalesced
#pragma unroll
    for (int p = 0; p < 2; p++) {
        int hw = (h0 + pr) * W_ + w0 + pc + p * 8;
        float* o = g_part + ((size_t)(chunk * N_ + n) * 100 + d * 25) * HW_ + hw;
#pragma unroll
        for (int m = 0; m < 12; m++) {
            float2 v = unpack2(acc[p][m]);
            o[(size_t)(2 * m) * HW_]     = v.x;
            o[(size_t)(2 * m + 1) * HW_] = v.y;
        }
        o[(size_t)24 * HW_] = acc24[p];
    }
}

// ---------------- K2b: sum partials + bias + softmax over 25 k -------------
__global__ void softmax_kernel(const float* __restrict__ bEnc) {
    int tid = threadIdx.x;
    int d = tid >> 6;
    int p = blockIdx.x * 64 + (tid & 63);
    int n = p >> 12, hw = p & 4095;

    float v[25];
#pragma unroll
    for (int k = 0; k < 25; k++) {
        float s = bEnc[k * 4 + d];
        size_t base = ((size_t)n * 100 + d * 25 + k) * HW_ + hw;
#pragma unroll
        for (int c = 0; c < NCHUNK_; c++)
            s += g_part[(size_t)c * N_ * 100 * HW_ + base];
        v[k] = s;
    }

    float mx = v[0];
#pragma unroll
    for (int k = 1; k < 25; k++) mx = fmaxf(mx, v[k]);
    float s = 0.f;
#pragma unroll
    for (int k = 0; k < 25; k++) {
        float e = __expf(v[k] - mx);
        v[k] = e;
        s += e;
    }
    float inv = 1.f / s;

    float* o = g_kern + ((size_t)n * 100 + d * 25) * HW_ + hw;
#pragma unroll
    for (int k = 0; k < 25; k++) o[(size_t)k * HW_] = v[k] * inv;
}

// ---------------- K4: reassembly + pixel shuffle + bias (f32x2) ------------
// grid: (64 tiles, 8 o-blocks of 32, 4 n); block 256 = 64 px * 4 oq
__global__ void carafe_out_kernel(const float* __restrict__ bOut,
                                  float* __restrict__ out) {
    __shared__ float yp[144][36];                 // [yy*12+xx][o], pad 36
    __shared__ __align__(16) float ks[64 * 100];  // [px][k*4 + d]

    int n  = blockIdx.z;
    int o0 = blockIdx.y * 32;
    int bx = blockIdx.x;
    int h0 = (bx >> 3) * 8, w0 = (bx & 7) * 8;
    int tid = threadIdx.x;

    for (int idx = tid; idx < 32 * 144; idx += 256) {
        int o = idx / 144, pos = idx % 144;
        int yy = pos / 12, xx = pos % 12;
        int gh = h0 - 2 + yy, gw = w0 - 2 + xx;
        float v = 0.f;
        if (gh >= 0 && gh < H_ && gw >= 0 && gw < W_)
            v = g_y[(((size_t)n * OUTC_ + o0 + o) * H_ + gh) * W_ + gw];
        yp[pos][o] = v;
    }
    for (int idx = tid; idx < 6400; idx += 256) {
        int r = idx >> 6;
        int px = idx & 63;
        int dd = r / 25, k = r % 25;
        int h = h0 + (px >> 3), w = w0 + (px & 7);
        ks[px * 100 + k * 4 + dd] =
            g_kern[((size_t)n * 100 + r) * HW_ + h * W_ + w];
    }
    __syncthreads();

    int px = tid >> 2, oq = tid & 3;
    int pr = px >> 3, pc = px & 7;

    unsigned long long acc[8][2];
#pragma unroll
    for (int i = 0; i < 8; i++) { acc[i][0] = 0ull; acc[i][1] = 0ull; }

    for (int kh = 0; kh < 5; kh++) {
#pragma unroll
        for (int kw = 0; kw < 5; kw++) {
            ulonglong2 kv2 = *(const ulonglong2*)&ks[px * 100 + (kh * 5 + kw) * 4];
            const float* yr = &yp[(pr + kh) * 12 + pc + kw][oq];
#pragma unroll
            for (int i = 0; i < 8; i++) {
                unsigned long long yv2 = pack2(yr[i * 4]);
                acc[i][0] = fma2(kv2.x, yv2, acc[i][0]);
                acc[i][1] = fma2(kv2.y, yv2, acc[i][1]);
            }
        }
    }

    int oy = 2 * (h0 + pr);
    int ox = 2 * (w0 + pc);
#pragma unroll
    for (int i = 0; i < 8; i++) {
        int o = o0 + oq + 4 * i;
        float b = bOut[o];
        float* p = out + (((size_t)n * OUTC_ + o) * HO_ + oy) * HO_ + ox;
        float2 r0 = unpack2(acc[i][0]);
        float2 r1 = unpack2(acc[i][1]);
        r0.x += b; r0.y += b; r1.x += b; r1.y += b;
        *(float2*)p = r0;
        *(float2*)(p + HO_) = r1;
    }
}

// ---------------- launch ----------------------------------------------------
extern "C" void kernel_launch(void* const* d_in, const int* in_sizes, int n_in,
                              void* d_out, int out_size) {
    (void)in_sizes; (void)n_in; (void)out_size;
    const float* x      = (const float*)d_in[0];
    const float* w_down = (const float*)d_in[1];
    const float* b_down = (const float*)d_in[2];
    const float* w_enc  = (const float*)d_in[3];
    const float* b_enc  = (const float*)d_in[4];
    const float* w_out  = (const float*)d_in[5];
    const float* b_out  = (const float*)d_in[6];
    float* out = (float*)d_out;

    float *t1p, *yp_;
    cudaGetSymbolAddress((void**)&t1p, g_t1);
    cudaGetSymbolAddress((void**)&yp_, g_y);

    // K0: enc weight transpose
    wt_kernel<<<(CM_ * 9 * 112 + 255) / 256, 256>>>(w_enc);
    // K1: down 1x1 conv -> g_t1
    conv1x1_kernel<<<dim3(1, 64, 4), 256>>>(x, w_down, b_down, t1p, CM_, 1);
    // K2a: enc 3x3 conv partials -> g_part
    enc_part_kernel<<<dim3(32, NCHUNK_, 4), 256>>>();
    // K2b: sum + softmax -> g_kern (channel-major)
    softmax_kernel<<<256, 256>>>(b_enc);
    // K3: out 1x1 conv on low-res -> g_y (bias deferred)
    conv1x1_kernel<<<dim3(4, 64, 4), 256>>>(x, w_out, nullptr, yp_, OUTC_, 0);
    // K4: reassembly + pixel shuffle + bias -> out
    carafe_out_kernel<<<dim3(64, 8, 4), 256>>>(b_out, out);
}

// round 4
// speedup vs baseline: 1.5078x; 1.0641x over previous
#include <cuda_runtime.h>

#define N_      4
#define H_      64
#define W_      64
#define INC_    256
#define CM_     64
#define OUTC_   256
#define HW_     (H_ * W_)       // 4096
#define HO_     (2 * H_)        // 128
#define NCHUNK_ 4               // ic chunks for enc conv (16 ic each)

// ---------------- scratch (device globals; no allocation allowed) ----------
__device__ float g_t1[N_ * CM_ * HW_];              // down-conv output   (4 MB)
__device__ float g_y [N_ * OUTC_ * HW_];            // out-conv on lowres (16 MB)
__device__ float g_kern[N_ * 100 * HW_];            // softmax kernels, channel-major
__device__ float g_part[NCHUNK_ * N_ * 100 * HW_];  // enc conv partials  (26 MB)
__device__ float g_wt[CM_ * 9 * 112];               // transposed enc weights
__device__ float g_wto[INC_ * OUTC_];               // w_out transposed [k][m]
__device__ float g_wtd[INC_ * CM_];                 // w_down transposed [k][m]

__device__ __forceinline__ unsigned long long fma2(unsigned long long a,
                                                   unsigned long long b,
                                                   unsigned long long c) {
    unsigned long long d;
    asm("fma.rn.f32x2 %0, %1, %2, %3;" : "=l"(d) : "l"(a), "l"(b), "l"(c));
    return d;
}
__device__ __forceinline__ unsigned long long pack2(float x) {
    unsigned long long r;
    asm("mov.b64 %0, {%1, %1};" : "=l"(r) : "f"(x));
    return r;
}
__device__ __forceinline__ float2 unpack2(unsigned long long a) {
    float2 r;
    asm("mov.b64 {%0, %1}, %2;" : "=f"(r.x), "=f"(r.y) : "l"(a));
    return r;
}

// ---------------- K0: all weight transposes ---------------------------------
// [0, 64512): enc weights -> g_wt [ic][tap][d][k pad 28]
// [64512, 130048): w_out -> g_wto [k][m]
// [130048, 146432): w_down -> g_wtd [k][m]
__global__ void wt_kernel(const float* __restrict__ w_enc,
                          const float* __restrict__ w_out,
                          const float* __restrict__ w_down) {
    int idx = blockIdx.x * 256 + threadIdx.x;
    if (idx < 64512) {
        int ic  = idx / (9 * 112);
        int r   = idx % (9 * 112);
        int t   = r / 112;
        int dk  = r % 112;
        int d   = dk / 28;
        int k   = dk % 28;
        float v = 0.f;
        if (k < 25) v = w_enc[((k * 4 + d) * CM_ + ic) * 9 + t];
        g_wt[idx] = v;
    } else if (idx < 130048) {
        int j = idx - 64512;
        int k = j >> 8, m = j & 255;
        g_wto[j] = w_out[m * INC_ + k];
    } else if (idx < 146432) {
        int j = idx - 130048;
        int k = j >> 6, m = j & 63;
        g_wtd[j] = w_down[m * INC_ + k];
    }
}

// ---------------- K1/K3: 1x1 conv as tiled SGEMM (f32x2, prefetch) ---------
// Y[n][m][p] = sum_k Wt[k][m] * X[n][k][p] (+ bias[m]); Wt row stride = M
__global__ void __launch_bounds__(256) conv1x1_kernel(
        const float* __restrict__ X,
        const float* __restrict__ Wt,
        const float* __restrict__ bias,
        float* __restrict__ Y,
        int M, int addBias) {
    __shared__ __align__(16) float As[32][64];   // [k][m]
    __shared__ __align__(16) float Bs[32][64];   // [k][p]

    int n  = blockIdx.z;
    int m0 = blockIdx.x * 64;
    int p0 = blockIdx.y * 64;
    int tid = threadIdx.x;
    int tr = tid >> 4;
    int tc = tid & 15;

    const float* Xn = X + (size_t)n * INC_ * HW_;

    float4 pa[2], pb[2];
#pragma unroll
    for (int it = 0; it < 2; it++) {
        int i = tid + it * 256;
        int rr = i >> 4, cc = i & 15;
        pa[it] = *(const float4*)(Wt + (size_t)rr * M + m0 + cc * 4);
        pb[it] = *(const float4*)(Xn + (size_t)rr * HW_ + p0 + cc * 4);
    }

    unsigned long long acc[4][2];
#pragma unroll
    for (int i = 0; i < 4; i++) { acc[i][0] = 0ull; acc[i][1] = 0ull; }

    for (int k0 = 0; k0 < INC_; k0 += 32) {
        __syncthreads();
#pragma unroll
        for (int it = 0; it < 2; it++) {
            int i = tid + it * 256;
            int rr = i >> 4, cc = i & 15;
            *(float4*)&As[rr][cc * 4] = pa[it];
            *(float4*)&Bs[rr][cc * 4] = pb[it];
        }
        __syncthreads();
        if (k0 + 32 < INC_) {
#pragma unroll
            for (int it = 0; it < 2; it++) {
                int i = tid + it * 256;
                int rr = i >> 4, cc = i & 15;
                pa[it] = *(const float4*)(Wt + (size_t)(k0 + 32 + rr) * M + m0 + cc * 4);
                pb[it] = *(const float4*)(Xn + (size_t)(k0 + 32 + rr) * HW_ + p0 + cc * 4);
            }
        }
#pragma unroll
        for (int kk = 0; kk < 32; kk++) {
            float4 a = *(const float4*)&As[kk][tr * 4];
            ulonglong2 b2 = *(const ulonglong2*)&Bs[kk][tc * 4];
            unsigned long long a0 = pack2(a.x), a1 = pack2(a.y);
            unsigned long long a2 = pack2(a.z), a3 = pack2(a.w);
            acc[0][0] = fma2(a0, b2.x, acc[0][0]); acc[0][1] = fma2(a0, b2.y, acc[0][1]);
            acc[1][0] = fma2(a1, b2.x, acc[1][0]); acc[1][1] = fma2(a1, b2.y, acc[1][1]);
            acc[2][0] = fma2(a2, b2.x, acc[2][0]); acc[2][1] = fma2(a2, b2.y, acc[2][1]);
            acc[3][0] = fma2(a3, b2.x, acc[3][0]); acc[3][1] = fma2(a3, b2.y, acc[3][1]);
        }
    }

    float* Yn = Y + ((size_t)n * M + m0) * HW_ + p0;
#pragma unroll
    for (int i = 0; i < 4; i++) {
        float bi = addBias ? bias[m0 + tr * 4 + i] : 0.f;
        float2 lo = unpack2(acc[i][0]);
        float2 hi = unpack2(acc[i][1]);
        float4 r;
        r.x = lo.x + bi; r.y = lo.y + bi;
        r.z = hi.x + bi; r.w = hi.y + bi;
        *(float4*)(Yn + (size_t)(tr * 4 + i) * HW_ + tc * 4) = r;
    }
}

// ---------------- K2a: enc 3x3 conv partials (16 ic per block, 2 passes) ---
__global__ void __launch_bounds__(256, 3) enc_part_kernel() {
    __shared__ float patch[8][10][40];
    __shared__ __align__(16) float ws[8][9][112];

    int n     = blockIdx.z;
    int chunk = blockIdx.y;
    int bx    = blockIdx.x;
    int h0 = (bx >> 2) * 8;
    int w0 = (bx & 3) * 16;
    int tid  = threadIdx.x;
    int wi   = tid >> 5, lane = tid & 31;
    int d    = wi >> 1;
    int pxg  = (wi & 1) * 32 + lane;
    int pr   = pxg >> 3, pc = pxg & 7;

    unsigned long long acc[2][12];
    float acc24[2];
#pragma unroll
    for (int p = 0; p < 2; p++) {
        acc24[p] = 0.f;
#pragma unroll
        for (int m = 0; m < 12; m++) acc[p][m] = 0ull;
    }

    for (int sc = 0; sc < 2; sc++) {
        int icbase = chunk * 16 + sc * 8;
        __syncthreads();
        for (int idx = tid; idx < 1440; idx += 256) {
            int ic = idx / 180, rem = idx % 180;
            int r = rem / 18, c = rem % 18;
            int gh = h0 - 1 + r, gw = w0 - 1 + c;
            float v = 0.f;
            if (gh >= 0 && gh < H_ && gw >= 0 && gw < W_)
                v = g_t1[(((size_t)n * CM_ + icbase + ic) * H_ + gh) * W_ + gw];
            patch[ic][r][c] = v;
        }
        {
            const float* src = g_wt + (size_t)icbase * 9 * 112;
            float* dst = &ws[0][0][0];
            for (int idx = tid; idx < 8 * 9 * 112; idx += 256) dst[idx] = src[idx];
        }
        __syncthreads();

#pragma unroll 2
        for (int ici = 0; ici < 8; ici++) {
#pragma unroll
            for (int t = 0; t < 9; t++) {
                int r = t / 3, c = t % 3;
                float va = patch[ici][pr + r][pc + c];
                float vb = patch[ici][pr + r][pc + 8 + c];
                unsigned long long va2 = pack2(va);
                unsigned long long vb2 = pack2(vb);
                const ulonglong2* wp = (const ulonglong2*)&ws[ici][t][d * 28];
#pragma unroll
                for (int q = 0; q < 6; q++) {
                    ulonglong2 w2 = wp[q];
                    acc[0][2 * q + 0] = fma2(w2.x, va2, acc[0][2 * q + 0]);
                    acc[0][2 * q + 1] = fma2(w2.y, va2, acc[0][2 * q + 1]);
                    acc[1][2 * q + 0] = fma2(w2.x, vb2, acc[1][2 * q + 0]);
                    acc[1][2 * q + 1] = fma2(w2.y, vb2, acc[1][2 * q + 1]);
                }
                float w24 = ws[ici][t][d * 28 + 24];
                acc24[0] += w24 * va;
                acc24[1] += w24 * vb;
            }
        }
    }

#pragma unroll
    for (int p = 0; p < 2; p++) {
        int hw = (h0 + pr) * W_ + w0 + pc + p * 8;
        float* o = g_part + ((size_t)(chunk * N_ + n) * 100 + d * 25) * HW_ + hw;
#pragma unroll
        for (int m = 0; m < 12; m++) {
            float2 v = unpack2(acc[p][m]);
            o[(size_t)(2 * m) * HW_]     = v.x;
            o[(size_t)(2 * m + 1) * HW_] = v.y;
        }
        o[(size_t)24 * HW_] = acc24[p];
    }
}

// ---------------- K2b: sum partials + bias + softmax over 25 k -------------
__global__ void softmax_kernel(const float* __restrict__ bEnc) {
    int tid = threadIdx.x;
    int d = tid >> 6;
    int p = blockIdx.x * 64 + (tid & 63);
    int n = p >> 12, hw = p & 4095;

    float v[25];
#pragma unroll
    for (int k = 0; k < 25; k++) {
        float s = bEnc[k * 4 + d];
        size_t base = ((size_t)n * 100 + d * 25 + k) * HW_ + hw;
#pragma unroll
        for (int c = 0; c < NCHUNK_; c++)
            s += g_part[(size_t)c * N_ * 100 * HW_ + base];
        v[k] = s;
    }

    float mx = v[0];
#pragma unroll
    for (int k = 1; k < 25; k++) mx = fmaxf(mx, v[k]);
    float s = 0.f;
#pragma unroll
    for (int k = 0; k < 25; k++) {
        float e = __expf(v[k] - mx);
        v[k] = e;
        s += e;
    }
    float inv = 1.f / s;

    float* o = g_kern + ((size_t)n * 100 + d * 25) * HW_ + hw;
#pragma unroll
    for (int k = 0; k < 25; k++) o[(size_t)k * HW_] = v[k] * inv;
}

// ---------------- K4: reassembly + pixel shuffle + bias (f32x2) ------------
__global__ void __launch_bounds__(256) carafe_out_kernel(
        const float* __restrict__ bOut, float* __restrict__ out) {
    __shared__ float yp[144][36];
    __shared__ __align__(16) float ks[64 * 100];

    int n  = blockIdx.z;
    int o0 = blockIdx.y * 32;
    int bx = blockIdx.x;
    int h0 = (bx >> 3) * 8, w0 = (bx & 7) * 8;
    int tid = threadIdx.x;

    for (int idx = tid; idx < 32 * 144; idx += 256) {
        int o = idx / 144, pos = idx % 144;
        int yy = pos / 12, xx = pos % 12;
        int gh = h0 - 2 + yy, gw = w0 - 2 + xx;
        float v = 0.f;
        if (gh >= 0 && gh < H_ && gw >= 0 && gw < W_)
            v = g_y[(((size_t)n * OUTC_ + o0 + o) * H_ + gh) * W_ + gw];
        yp[pos][o] = v;
    }
    for (int idx = tid; idx < 6400; idx += 256) {
        int r = idx >> 6;
        int px = idx & 63;
        int dd = r / 25, k = r % 25;
        int h = h0 + (px >> 3), w = w0 + (px & 7);
        ks[px * 100 + k * 4 + dd] =
            g_kern[((size_t)n * 100 + r) * HW_ + h * W_ + w];
    }
    __syncthreads();

    int px = tid >> 2, oq = tid & 3;
    int pr = px >> 3, pc = px & 7;

    unsigned long long acc[8][2];
#pragma unroll
    for (int i = 0; i < 8; i++) { acc[i][0] = 0ull; acc[i][1] = 0ull; }

    for (int kh = 0; kh < 5; kh++) {
#pragma unroll
        for (int kw = 0; kw < 5; kw++) {
            ulonglong2 kv2 = *(const ulonglong2*)&ks[px * 100 + (kh * 5 + kw) * 4];
            const float* yr = &yp[(pr + kh) * 12 + pc + kw][oq];
#pragma unroll
            for (int i = 0; i < 8; i++) {
                unsigned long long yv2 = pack2(yr[i * 4]);
                acc[i][0] = fma2(kv2.x, yv2, acc[i][0]);
                acc[i][1] = fma2(kv2.y, yv2, acc[i][1]);
            }
        }
    }

    int oy = 2 * (h0 + pr);
    int ox = 2 * (w0 + pc);
#pragma unroll
    for (int i = 0; i < 8; i++) {
        int o = o0 + oq + 4 * i;
        float b = bOut[o];
        float* p = out + (((size_t)n * OUTC_ + o) * HO_ + oy) * HO_ + ox;
        float2 r0 = unpack2(acc[i][0]);
        float2 r1 = unpack2(acc[i][1]);
        r0.x += b; r0.y += b; r1.x += b; r1.y += b;
        *(float2*)p = r0;
        *(float2*)(p + HO_) = r1;
    }
}

// ---------------- launch ----------------------------------------------------
extern "C" void kernel_launch(void* const* d_in, const int* in_sizes, int n_in,
                              void* d_out, int out_size) {
    (void)in_sizes; (void)n_in; (void)out_size;
    const float* x      = (const float*)d_in[0];
    const float* w_down = (const float*)d_in[1];
    const float* b_down = (const float*)d_in[2];
    const float* w_enc  = (const float*)d_in[3];
    const float* b_enc  = (const float*)d_in[4];
    const float* w_out  = (const float*)d_in[5];
    const float* b_out  = (const float*)d_in[6];
    float* out = (float*)d_out;

    float *t1p, *yp_, *wtop, *wtdp;
    cudaGetSymbolAddress((void**)&t1p,  g_t1);
    cudaGetSymbolAddress((void**)&yp_,  g_y);
    cudaGetSymbolAddress((void**)&wtop, g_wto);
    cudaGetSymbolAddress((void**)&wtdp, g_wtd);

    // fork-join side stream (host resources; created at launch/capture time only)
    cudaStream_t s1;
    cudaStreamCreateWithFlags(&s1, cudaStreamNonBlocking);
    cudaEvent_t evFork, evJoin;
    cudaEventCreateWithFlags(&evFork, cudaEventDisableTiming);
    cudaEventCreateWithFlags(&evJoin, cudaEventDisableTiming);

    // K0: all weight transposes (legacy stream)
    wt_kernel<<<572, 256>>>(w_enc, w_out, w_down);

    // fork: K3 out-conv chain on s1 (needs only x + g_wto)
    cudaEventRecord(evFork, 0);
    cudaStreamWaitEvent(s1, evFork, 0);
    conv1x1_kernel<<<dim3(4, 64, 4), 256, 0, s1>>>(x, wtop, nullptr, yp_, OUTC_, 0);
    cudaEventRecord(evJoin, s1);

    // main chain on legacy stream
    conv1x1_kernel<<<dim3(1, 64, 4), 256>>>(x, wtdp, b_down, t1p, CM_, 1);
    enc_part_kernel<<<dim3(32, NCHUNK_, 4), 256>>>();
    softmax_kernel<<<256, 256>>>(b_enc);

    // join, then K4
    cudaStreamWaitEvent(0, evJoin, 0);
    carafe_out_kernel<<<dim3(64, 8, 4), 256>>>(b_out, out);
}